// round 8
// baseline (speedup 1.0000x reference)
#include <cuda_runtime.h>
#include <math.h>

#define N_NODES 50000
#define N_EDGES 800000
#define HDIM 96
#define SDIM 48
#define FDIM 24

// output layout: update[N*96] | fwd_w[E] | rev_w[E] | z[N*96] | r[N*96]
#define OFF_FW 4800000L
#define OFF_RW 5600000L
#define OFF_Z  6400000L
#define OFF_R  11200000L

// ---------------- scratch (__device__ globals; no allocation allowed) ----------------
__device__ float g_u[N_NODES * 144];          // [x | x_s]
__device__ float g_Wpack[768 * 144];          // node-projection weights [M=768, K=144]
__device__ float g_bpack[768];                // b1f baked into Sf, b1r into Br
__device__ float g_W1e[384 * 24];             // edge-feature projection weights
__device__ float g_table[N_NODES * 768];      // per node: Sf(192)|Br(192)|Df(192)|Ar(192)
__device__ float g_pe[N_EDGES * 384];         // per edge: pe_f(192)|pe_r(192)
__device__ float g_expf[N_EDGES];             // exp(score_fwd)
__device__ float g_ssum[N_NODES];             // softmax denominators
__device__ float g_fwdnum[N_NODES * HDIM];    // softmax-weighted numerator
__device__ float g_revagg[N_NODES * HDIM];    // sigmoid-weighted rev aggregation
__device__ float g_gatein[N_NODES * 288];
__device__ float g_candin[N_NODES * 288];
__device__ float g_h[N_NODES * 288];
__device__ float g_cand[N_NODES * HDIM];

// ---------------- small helpers ----------------
__device__ __forceinline__ void red4(float* p, float a, float b, float c, float d) {
    asm volatile("red.global.add.v4.f32 [%0], {%1,%2,%3,%4};"
                 :: "l"(p), "f"(a), "f"(b), "f"(c), "f"(d) : "memory");
}

// ---------------- weight packing ----------------
__global__ void pack_node_weights(const float* __restrict__ fwdW1, const float* __restrict__ revW1,
                                  const float* __restrict__ fwdb1, const float* __restrict__ revb1)
{
    int idx = blockIdx.x * blockDim.x + threadIdx.x;
    int total = 768 * 144;
    for (; idx < total; idx += gridDim.x * blockDim.x) {
        int j = idx / 144;     // output unit (0..767)
        int k = idx % 144;     // node-feature index: 0..95 -> x, 96..143 -> x_s
        float v;
        if (j < 192) {                       // Sf: fwd, "s" side
            v = (k < 96) ? fwdW1[j * 312 + k] : fwdW1[j * 312 + 192 + (k - 96)];
        } else if (j < 384) {                // Br: rev, "d" side (applied at src)
            int j2 = j - 192;
            v = (k < 96) ? revW1[j2 * 312 + 96 + k] : revW1[j2 * 312 + 240 + (k - 96)];
        } else if (j < 576) {                // Df: fwd, "d" side
            int j3 = j - 384;
            v = (k < 96) ? fwdW1[j3 * 312 + 96 + k] : fwdW1[j3 * 312 + 240 + (k - 96)];
        } else {                             // Ar: rev, "s" side (applied at dest)
            int j4 = j - 576;
            v = (k < 96) ? revW1[j4 * 312 + k] : revW1[j4 * 312 + 192 + (k - 96)];
        }
        g_Wpack[j * 144 + k] = v;
        if (k == 0) {
            g_bpack[j] = (j < 192) ? fwdb1[j] : ((j < 384) ? revb1[j - 192] : 0.0f);
        }
    }
}

__global__ void pack_edge_weights(const float* __restrict__ fwdW1, const float* __restrict__ revW1)
{
    int idx = blockIdx.x * blockDim.x + threadIdx.x;
    if (idx >= 384 * 24) return;
    int j = idx / 24, k = idx % 24;
    g_W1e[idx] = (j < 192) ? fwdW1[j * 312 + 288 + k] : revW1[(j - 192) * 312 + 288 + k];
}

__global__ void build_u(const float* __restrict__ x, const float* __restrict__ x_s)
{
    long idx = (long)blockIdx.x * blockDim.x + threadIdx.x;
    long total = (long)N_NODES * 144;
    for (; idx < total; idx += (long)gridDim.x * blockDim.x) {
        int n = (int)(idx / 144), c = (int)(idx % 144);
        g_u[idx] = (c < 96) ? x[(long)n * 96 + c] : x_s[(long)n * 48 + (c - 96)];
    }
}

__global__ void zero_accum()
{
    long idx = (long)blockIdx.x * blockDim.x + threadIdx.x;
    long total = (long)N_NODES * (1 + 2 * HDIM);
    for (; idx < total; idx += (long)gridDim.x * blockDim.x) {
        if (idx < N_NODES) g_ssum[idx] = 0.0f;
        else if (idx < (long)N_NODES * (1 + HDIM)) g_fwdnum[idx - N_NODES] = 0.0f;
        else g_revagg[idx - (long)N_NODES * (1 + HDIM)] = 0.0f;
    }
}

// ---------------- generic tiled fp32 GEMM: C = act(A[N,K] @ W[M,K]^T + bias) ----------------
#define GBM 64
#define GBN 32
#define GBK 8
// acts: 0=none 1=relu 2=sigmoid 3=tanh
__global__ __launch_bounds__(128)
void gemm_kernel(const float* __restrict__ A, const float* __restrict__ W,
                 const float* __restrict__ bias, float* __restrict__ C,
                 int Nrows, int K, int M, int act)
{
    __shared__ float sA[GBK][GBM + 4];
    __shared__ float sW[GBK][GBN + 4];
    int tid = threadIdx.x;
    int tx = tid & 7;          // 0..7  -> col group (4 cols each)
    int ty = tid >> 3;         // 0..15 -> row group (4 rows each)
    int row0 = blockIdx.y * GBM;
    int col0 = blockIdx.x * GBN;

    float acc[4][4];
#pragma unroll
    for (int i = 0; i < 4; i++)
#pragma unroll
        for (int j = 0; j < 4; j++) acc[i][j] = 0.0f;

    for (int k0 = 0; k0 < K; k0 += GBK) {
#pragma unroll
        for (int s0 = 0; s0 < GBM * GBK; s0 += 128) {
            int s = s0 + tid;
            int r = s >> 3, kk = s & 7;
            int gr = row0 + r;
            sA[kk][r] = (gr < Nrows) ? A[(long)gr * K + k0 + kk] : 0.0f;
        }
#pragma unroll
        for (int s0 = 0; s0 < GBN * GBK; s0 += 128) {
            int s = s0 + tid;
            if (s < GBN * GBK) {
                int c = s >> 3, kk = s & 7;
                sW[kk][c] = W[(long)(col0 + c) * K + k0 + kk];
            }
        }
        __syncthreads();
#pragma unroll
        for (int kk = 0; kk < GBK; kk++) {
            float a[4], w[4];
            *(float4*)a = *(const float4*)&sA[kk][ty * 4];
            *(float4*)w = *(const float4*)&sW[kk][tx * 4];
#pragma unroll
            for (int i = 0; i < 4; i++)
#pragma unroll
                for (int j = 0; j < 4; j++) acc[i][j] = fmaf(a[i], w[j], acc[i][j]);
        }
        __syncthreads();
    }

#pragma unroll
    for (int i = 0; i < 4; i++) {
        int gr = row0 + ty * 4 + i;
        if (gr >= Nrows) continue;
#pragma unroll
        for (int j = 0; j < 4; j++) {
            int gc = col0 + tx * 4 + j;
            float v = acc[i][j] + (bias ? bias[gc] : 0.0f);
            if (act == 1) v = fmaxf(v, 0.0f);
            else if (act == 2) v = 1.0f / (1.0f + expf(-v));
            else if (act == 3) v = tanhf(v);
            C[(long)gr * M + gc] = v;
        }
    }
}

// ---------------- edge kernel: one warp per edge ----------------
__global__ __launch_bounds__(256)
void edge_kernel(const int* __restrict__ ei, const float* __restrict__ x,
                 const float* __restrict__ fwdW2, const float* __restrict__ fwdb2,
                 const float* __restrict__ revW2, const float* __restrict__ revb2,
                 float* __restrict__ out)
{
    __shared__ float sW2f[192], sW2r[192];
    int tid = threadIdx.x;
    if (tid < 192) { sW2f[tid] = fwdW2[tid]; sW2r[tid] = revW2[tid]; }
    __syncthreads();

    long e = (long)blockIdx.x * 8 + (tid >> 5);
    if (e >= N_EDGES) return;
    int lane = tid & 31;

    int src = ei[e];
    int dst = ei[N_EDGES + e];
    const float* srow = g_table + (long)src * 768;
    const float* drow = g_table + (long)dst * 768;
    const float* pe = g_pe + e * 384;

    float dotf = 0.0f, dotr = 0.0f;
#pragma unroll
    for (int i = 0; i < 6; i++) {
        int j = lane + 32 * i;
        float hf = srow[j] + drow[384 + j] + pe[j];
        dotf = fmaf(fmaxf(hf, 0.0f), sW2f[j], dotf);
        float hr = srow[192 + j] + drow[576 + j] + pe[192 + j];
        dotr = fmaf(fmaxf(hr, 0.0f), sW2r[j], dotr);
    }
#pragma unroll
    for (int o = 16; o > 0; o >>= 1) {
        dotf += __shfl_down_sync(0xffffffffu, dotf, o);
        dotr += __shfl_down_sync(0xffffffffu, dotr, o);
    }

    float efv = 0.0f, wr = 0.0f;
    if (lane == 0) {
        float rawf = dotf + fwdb2[0];
        float score = (rawf >= 0.0f ? rawf : 0.01f * rawf) * (1.0f / sqrtf(96.0f));
        efv = expf(score);     // max-free softmax (scores are tiny; shift-invariant)
        float rawr = dotr + revb2[0];
        wr = 1.0f / (1.0f + expf(-rawr));
        g_expf[e] = efv;
        out[OFF_RW + e] = wr;
        atomicAdd(&g_ssum[dst], efv);
    }
    efv = __shfl_sync(0xffffffffu, efv, 0);
    wr  = __shfl_sync(0xffffffffu, wr, 0);

    if (lane < 24) {
        float4 xs = ((const float4*)x)[(long)src * 24 + lane];
        red4(&g_fwdnum[(long)dst * 96 + lane * 4], xs.x * efv, xs.y * efv, xs.z * efv, xs.w * efv);
        float4 xd = ((const float4*)x)[(long)dst * 24 + lane];
        red4(&g_revagg[(long)src * 96 + lane * 4], xd.x * wr, xd.y * wr, xd.z * wr, xd.w * wr);
    }
}

__global__ void fwdw_kernel(const int* __restrict__ ei, float* __restrict__ out)
{
    long e = (long)blockIdx.x * blockDim.x + threadIdx.x;
    if (e >= N_EDGES) return;
    int dst = ei[N_EDGES + e];
    out[OFF_FW + e] = g_expf[e] / (g_ssum[dst] + 1e-9f);
}

__global__ void build_gatein(const float* __restrict__ x)
{
    long idx = (long)blockIdx.x * blockDim.x + threadIdx.x;
    long total = (long)N_NODES * 288;
    for (; idx < total; idx += (long)gridDim.x * blockDim.x) {
        int n = (int)(idx / 288), c = (int)(idx % 288);
        float v;
        if (c < 96)       v = x[(long)n * 96 + c];
        else if (c < 192) v = g_fwdnum[(long)n * 96 + (c - 96)] / (g_ssum[n] + 1e-9f);
        else              v = g_revagg[(long)n * 96 + (c - 192)];
        g_gatein[idx] = v;
    }
}

__global__ void build_candin(const float* __restrict__ x, const float* __restrict__ out)
{
    long idx = (long)blockIdx.x * blockDim.x + threadIdx.x;
    long total = (long)N_NODES * 288;
    for (; idx < total; idx += (long)gridDim.x * blockDim.x) {
        int n = (int)(idx / 288), c = (int)(idx % 288);
        float v;
        if (c < 96) v = out[OFF_R + (long)n * 96 + c] * x[(long)n * 96 + c];
        else        v = g_gatein[idx];
        g_candin[idx] = v;
    }
}

__global__ void update_kernel(const float* __restrict__ x, float* __restrict__ out)
{
    long idx = (long)blockIdx.x * blockDim.x + threadIdx.x;
    long total = (long)N_NODES * 96;
    if (idx >= total) return;
    float z = out[OFF_Z + idx];
    out[idx] = (1.0f - z) * x[idx] + z * g_cand[idx];
}

// ---------------- launcher ----------------
extern "C" void kernel_launch(void* const* d_in, const int* in_sizes, int n_in,
                              void* d_out, int out_size)
{
    const float* x     = (const float*)d_in[0];
    const float* x_s   = (const float*)d_in[1];
    const float* efeat = (const float*)d_in[2];
    const int*   ei    = (const int*)d_in[3];
    const float* fwdW1 = (const float*)d_in[4];
    const float* fwdb1 = (const float*)d_in[5];
    const float* fwdW2 = (const float*)d_in[6];
    const float* fwdb2 = (const float*)d_in[7];
    const float* revW1 = (const float*)d_in[8];
    const float* revb1 = (const float*)d_in[9];
    const float* revW2 = (const float*)d_in[10];
    const float* revb2 = (const float*)d_in[11];
    const float* rstW1 = (const float*)d_in[12];
    const float* rstb1 = (const float*)d_in[13];
    const float* rstW2 = (const float*)d_in[14];
    const float* rstb2 = (const float*)d_in[15];
    const float* updW1 = (const float*)d_in[16];
    const float* updb1 = (const float*)d_in[17];
    const float* updW2 = (const float*)d_in[18];
    const float* updb2 = (const float*)d_in[19];
    const float* cndW1 = (const float*)d_in[20];
    const float* cndb1 = (const float*)d_in[21];
    const float* cndW2 = (const float*)d_in[22];
    const float* cndb2 = (const float*)d_in[23];
    float* out = (float*)d_out;

    float *p_u, *p_Wpack, *p_bpack, *p_W1e, *p_table, *p_pe, *p_gatein, *p_candin, *p_h, *p_cand;
    cudaGetSymbolAddress((void**)&p_u, g_u);
    cudaGetSymbolAddress((void**)&p_Wpack, g_Wpack);
    cudaGetSymbolAddress((void**)&p_bpack, g_bpack);
    cudaGetSymbolAddress((void**)&p_W1e, g_W1e);
    cudaGetSymbolAddress((void**)&p_table, g_table);
    cudaGetSymbolAddress((void**)&p_pe, g_pe);
    cudaGetSymbolAddress((void**)&p_gatein, g_gatein);
    cudaGetSymbolAddress((void**)&p_candin, g_candin);
    cudaGetSymbolAddress((void**)&p_h, g_h);
    cudaGetSymbolAddress((void**)&p_cand, g_cand);

    // 1. pack weights
    pack_node_weights<<<432, 256>>>(fwdW1, revW1, fwdb1, revb1);
    pack_edge_weights<<<36, 256>>>(fwdW1, revW1);
    build_u<<<7040, 256>>>(x, x_s);
    zero_accum<<<9432, 256>>>();

    // 2. node table: [N,144] @ [144,768]^T-style packed -> [N,768], bias baked
    {
        dim3 grid(768 / GBN, (N_NODES + GBM - 1) / GBM);
        gemm_kernel<<<grid, 128>>>(p_u, p_Wpack, p_bpack, p_table, N_NODES, 144, 768, 0);
    }
    // 3. edge-feature projection: [E,24] @ [24,384] -> [E,384]
    {
        dim3 grid(384 / GBN, (N_EDGES + GBM - 1) / GBM);
        gemm_kernel<<<grid, 128>>>(efeat, p_W1e, nullptr, p_pe, N_EDGES, 24, 384, 0);
    }
    // 4. edge pass: attention scores + aggregations
    edge_kernel<<<N_EDGES / 8, 256>>>(ei, x, fwdW2, fwdb2, revW2, revb2, out);
    // 5. normalized fwd weights
    fwdw_kernel<<<(N_EDGES + 255) / 256, 256>>>(ei, out);
    // 6. GRU
    build_gatein<<<14063, 256>>>(x);
    {
        dim3 g288(288 / GBN, (N_NODES + GBM - 1) / GBM);
        dim3 g96(96 / GBN, (N_NODES + GBM - 1) / GBM);
        gemm_kernel<<<g288, 128>>>(p_gatein, rstW1, rstb1, p_h, N_NODES, 288, 288, 1);
        gemm_kernel<<<g96, 128>>>(p_h, rstW2, rstb2, out + OFF_R, N_NODES, 288, 96, 2);
        gemm_kernel<<<g288, 128>>>(p_gatein, updW1, updb1, p_h, N_NODES, 288, 288, 1);
        gemm_kernel<<<g96, 128>>>(p_h, updW2, updb2, out + OFF_Z, N_NODES, 288, 96, 2);
        build_candin<<<14063, 256>>>(x, out);
        gemm_kernel<<<g288, 128>>>(p_candin, cndW1, cndb1, p_h, N_NODES, 288, 288, 1);
        gemm_kernel<<<g96, 128>>>(p_h, cndW2, cndb2, p_cand, N_NODES, 288, 96, 3);
    }
    update_kernel<<<(N_NODES * 96 + 255) / 256, 256>>>(x, out);
}

// round 14
// speedup vs baseline: 1.2758x; 1.2758x over previous
#include <cuda_runtime.h>
#include <math.h>

#define N_NODES 50000
#define N_EDGES 800000
#define HDIM 96
#define SDIM 48
#define FDIM 24

// output layout: update[N*96] | fwd_w[E] | rev_w[E] | z[N*96] | r[N*96]
#define OFF_FW 4800000L
#define OFF_RW 5600000L
#define OFF_Z  6400000L
#define OFF_R  11200000L

typedef unsigned int u32;
typedef unsigned long long u64;

// ---------------- scratch (__device__ globals; no allocation allowed) ----------------
__device__ float g_u[N_NODES * 144];          // [x | x_s]
__device__ float g_Wpack[768 * 144];          // node-projection weights [M=768, K=144]
__device__ float g_bpack[768];                // b1f baked into Sf, b1r into Br
__device__ float g_W1e[384 * 24];             // edge-feature projection weights
__device__ float g_table[N_NODES * 768];      // per node: Sf(192)|Br(192)|Df(192)|Ar(192)
__device__ float g_pe[N_EDGES * 384];         // per edge: pe_f(192)|pe_r(192)
__device__ float g_expf[N_EDGES];             // exp(score_fwd)
__device__ float g_ssum[N_NODES];             // softmax denominators
__device__ float g_fwdnum[N_NODES * HDIM];    // softmax-weighted numerator
__device__ float g_revagg[N_NODES * HDIM];    // sigmoid-weighted rev aggregation
__device__ float g_gatein[N_NODES * 288];
__device__ float g_candin[N_NODES * 288];
__device__ float g_h[N_NODES * 288];
__device__ float g_cand[N_NODES * HDIM];

// ---------------- small helpers ----------------
__device__ __forceinline__ void red4(float* p, float a, float b, float c, float d) {
    asm volatile("red.global.add.v4.f32 [%0], {%1,%2,%3,%4};"
                 :: "l"(p), "f"(a), "f"(b), "f"(c), "f"(d) : "memory");
}

__device__ __forceinline__ u32 f2tf(float f) {
    u32 r;
    asm("cvt.rna.tf32.f32 %0, %1;" : "=r"(r) : "f"(f));
    return r;
}

// ---------------- weight packing ----------------
__global__ void pack_node_weights(const float* __restrict__ fwdW1, const float* __restrict__ revW1,
                                  const float* __restrict__ fwdb1, const float* __restrict__ revb1)
{
    int idx = blockIdx.x * blockDim.x + threadIdx.x;
    int total = 768 * 144;
    for (; idx < total; idx += gridDim.x * blockDim.x) {
        int j = idx / 144;     // output unit (0..767)
        int k = idx % 144;     // node-feature index: 0..95 -> x, 96..143 -> x_s
        float v;
        if (j < 192) {                       // Sf: fwd, "s" side
            v = (k < 96) ? fwdW1[j * 312 + k] : fwdW1[j * 312 + 192 + (k - 96)];
        } else if (j < 384) {                // Br: rev, "d" side (applied at src)
            int j2 = j - 192;
            v = (k < 96) ? revW1[j2 * 312 + 96 + k] : revW1[j2 * 312 + 240 + (k - 96)];
        } else if (j < 576) {                // Df: fwd, "d" side
            int j3 = j - 384;
            v = (k < 96) ? fwdW1[j3 * 312 + 96 + k] : fwdW1[j3 * 312 + 240 + (k - 96)];
        } else {                             // Ar: rev, "s" side (applied at dest)
            int j4 = j - 576;
            v = (k < 96) ? revW1[j4 * 312 + k] : revW1[j4 * 312 + 192 + (k - 96)];
        }
        g_Wpack[j * 144 + k] = v;
        if (k == 0) {
            g_bpack[j] = (j < 192) ? fwdb1[j] : ((j < 384) ? revb1[j - 192] : 0.0f);
        }
    }
}

__global__ void pack_edge_weights(const float* __restrict__ fwdW1, const float* __restrict__ revW1)
{
    int idx = blockIdx.x * blockDim.x + threadIdx.x;
    if (idx >= 384 * 24) return;
    int j = idx / 24, k = idx % 24;
    g_W1e[idx] = (j < 192) ? fwdW1[j * 312 + 288 + k] : revW1[(j - 192) * 312 + 288 + k];
}

__global__ void build_u(const float* __restrict__ x, const float* __restrict__ x_s)
{
    long idx = (long)blockIdx.x * blockDim.x + threadIdx.x;
    long total = (long)N_NODES * 144;
    for (; idx < total; idx += (long)gridDim.x * blockDim.x) {
        int n = (int)(idx / 144), c = (int)(idx % 144);
        g_u[idx] = (c < 96) ? x[(long)n * 96 + c] : x_s[(long)n * 48 + (c - 96)];
    }
}

__global__ void zero_accum()
{
    long idx = (long)blockIdx.x * blockDim.x + threadIdx.x;
    long total = (long)N_NODES * (1 + 2 * HDIM);
    for (; idx < total; idx += (long)gridDim.x * blockDim.x) {
        if (idx < N_NODES) g_ssum[idx] = 0.0f;
        else if (idx < (long)N_NODES * (1 + HDIM)) g_fwdnum[idx - N_NODES] = 0.0f;
        else g_revagg[idx - (long)N_NODES * (1 + HDIM)] = 0.0f;
    }
}

// ============================================================================
// mma.sync tf32 GEMM:  C[r, 0..M) = act( A[r, 0..K) @ W[m, 0..K)^T + bias )
// CTA tile 64x64, 4 warps of 32x32 (2x4 m16n8k8 frags), K chunked by 32.
// KPAD=36 -> fragment smem reads are bank-conflict-free permutations.
// acts: 0=none 1=relu 2=sigmoid 3=tanh
// ============================================================================
#define MT 64
#define NT 64
#define KC 32
#define KPAD 36

__global__ __launch_bounds__(128)
void mma_gemm(const float* __restrict__ A, const float* __restrict__ W,
              const float* __restrict__ bias, float* __restrict__ C,
              int Nrows, int K, int M, int act)
{
    __shared__ u32 sA[MT * KPAD];
    __shared__ u32 sW[NT * KPAD];
    int tid = threadIdx.x;
    int warp = tid >> 5, lane = tid & 31;
    int qr = lane >> 2, qc = lane & 3;
    int m_off = (warp & 1) << 5;
    int n_off = (warp >> 1) << 5;
    long row0 = (long)blockIdx.y * MT;
    int col0 = blockIdx.x * NT;

    float acc[2][4][4];
#pragma unroll
    for (int mf = 0; mf < 2; mf++)
#pragma unroll
        for (int nf = 0; nf < 4; nf++)
#pragma unroll
            for (int i = 0; i < 4; i++) acc[mf][nf][i] = 0.0f;

    for (int k0 = 0; k0 < K; k0 += KC) {
        // ---- A chunk: 64 rows x 32 cols ----
#pragma unroll
        for (int i = 0; i < 4; i++) {
            int s = tid + (i << 7);
            int r = s >> 3, q = (s & 7) << 2;
            long gr = row0 + r;
            int kk = k0 + q;
            float4 v = make_float4(0.f, 0.f, 0.f, 0.f);
            if (gr < Nrows) {
                if (kk + 4 <= K) v = *(const float4*)(A + gr * K + kk);
                else {
                    if (kk < K)     v.x = A[gr * K + kk];
                    if (kk + 1 < K) v.y = A[gr * K + kk + 1];
                    if (kk + 2 < K) v.z = A[gr * K + kk + 2];
                    if (kk + 3 < K) v.w = A[gr * K + kk + 3];
                }
            }
            *(uint4*)&sA[r * KPAD + q] = make_uint4(f2tf(v.x), f2tf(v.y), f2tf(v.z), f2tf(v.w));
        }
        // ---- W chunk: 64 out-channels x 32 cols ----
#pragma unroll
        for (int i = 0; i < 4; i++) {
            int s = tid + (i << 7);
            int r = s >> 3, q = (s & 7) << 2;
            int gc = col0 + r;
            int kk = k0 + q;
            float4 v = make_float4(0.f, 0.f, 0.f, 0.f);
            if (gc < M) {
                if (kk + 4 <= K) v = *(const float4*)(W + (long)gc * K + kk);
                else {
                    if (kk < K)     v.x = W[(long)gc * K + kk];
                    if (kk + 1 < K) v.y = W[(long)gc * K + kk + 1];
                    if (kk + 2 < K) v.z = W[(long)gc * K + kk + 2];
                    if (kk + 3 < K) v.w = W[(long)gc * K + kk + 3];
                }
            }
            *(uint4*)&sW[r * KPAD + q] = make_uint4(f2tf(v.x), f2tf(v.y), f2tf(v.z), f2tf(v.w));
        }
        __syncthreads();

#pragma unroll
        for (int ks = 0; ks < 4; ks++) {
            int kb = ks << 3;
            u32 a[2][4];
#pragma unroll
            for (int mf = 0; mf < 2; mf++) {
                int rb = (m_off + (mf << 4) + qr) * KPAD + kb + qc;
                a[mf][0] = sA[rb];
                a[mf][1] = sA[rb + 8 * KPAD];
                a[mf][2] = sA[rb + 4];
                a[mf][3] = sA[rb + 8 * KPAD + 4];
            }
#pragma unroll
            for (int nf = 0; nf < 4; nf++) {
                int rb = (n_off + (nf << 3) + qr) * KPAD + kb + qc;
                u32 b0 = sW[rb], b1 = sW[rb + 4];
#pragma unroll
                for (int mf = 0; mf < 2; mf++) {
                    asm("mma.sync.aligned.m16n8k8.row.col.f32.tf32.tf32.f32 "
                        "{%0,%1,%2,%3}, {%4,%5,%6,%7}, {%8,%9}, {%0,%1,%2,%3};"
                        : "+f"(acc[mf][nf][0]), "+f"(acc[mf][nf][1]),
                          "+f"(acc[mf][nf][2]), "+f"(acc[mf][nf][3])
                        : "r"(a[mf][0]), "r"(a[mf][1]), "r"(a[mf][2]), "r"(a[mf][3]),
                          "r"(b0), "r"(b1));
                }
            }
        }
        __syncthreads();
    }

    // ---- epilogue: bias + act, float2 stores ----
#pragma unroll
    for (int mf = 0; mf < 2; mf++) {
#pragma unroll
        for (int h = 0; h < 2; h++) {
            long gr = row0 + m_off + (mf << 4) + qr + h * 8;
            if (gr >= Nrows) continue;
#pragma unroll
            for (int nf = 0; nf < 4; nf++) {
                int gc = col0 + n_off + (nf << 3) + (qc << 1);
                if (gc >= M) continue;
                float v0 = acc[mf][nf][h * 2 + 0];
                float v1 = acc[mf][nf][h * 2 + 1];
                if (bias) { v0 += bias[gc]; v1 += bias[gc + 1]; }
                if (act == 1) { v0 = fmaxf(v0, 0.0f); v1 = fmaxf(v1, 0.0f); }
                else if (act == 2) {
                    v0 = 1.0f / (1.0f + expf(-v0));
                    v1 = 1.0f / (1.0f + expf(-v1));
                } else if (act == 3) { v0 = tanhf(v0); v1 = tanhf(v1); }
                *(float2*)(C + gr * M + gc) = make_float2(v0, v1);
            }
        }
    }
}

// ---------------- edge kernel: one warp per edge ----------------
__global__ __launch_bounds__(256)
void edge_kernel(const int* __restrict__ ei, const float* __restrict__ x,
                 const float* __restrict__ fwdW2, const float* __restrict__ fwdb2,
                 const float* __restrict__ revW2, const float* __restrict__ revb2,
                 float* __restrict__ out)
{
    __shared__ float sW2f[192], sW2r[192];
    int tid = threadIdx.x;
    if (tid < 192) { sW2f[tid] = fwdW2[tid]; sW2r[tid] = revW2[tid]; }
    __syncthreads();

    long e = (long)blockIdx.x * 8 + (tid >> 5);
    if (e >= N_EDGES) return;
    int lane = tid & 31;

    int src = ei[e];
    int dst = ei[N_EDGES + e];
    const float* srow = g_table + (long)src * 768;
    const float* drow = g_table + (long)dst * 768;
    const float* pe = g_pe + e * 384;

    float dotf = 0.0f, dotr = 0.0f;
#pragma unroll
    for (int i = 0; i < 6; i++) {
        int j = lane + 32 * i;
        float hf = srow[j] + drow[384 + j] + pe[j];
        dotf = fmaf(fmaxf(hf, 0.0f), sW2f[j], dotf);
        float hr = srow[192 + j] + drow[576 + j] + pe[192 + j];
        dotr = fmaf(fmaxf(hr, 0.0f), sW2r[j], dotr);
    }
#pragma unroll
    for (int o = 16; o > 0; o >>= 1) {
        dotf += __shfl_down_sync(0xffffffffu, dotf, o);
        dotr += __shfl_down_sync(0xffffffffu, dotr, o);
    }

    float efv = 0.0f, wr = 0.0f;
    if (lane == 0) {
        float rawf = dotf + fwdb2[0];
        float score = (rawf >= 0.0f ? rawf : 0.01f * rawf) * (1.0f / sqrtf(96.0f));
        efv = expf(score);     // max-free softmax (scores are tiny; shift-invariant)
        float rawr = dotr + revb2[0];
        wr = 1.0f / (1.0f + expf(-rawr));
        g_expf[e] = efv;
        out[OFF_RW + e] = wr;
        atomicAdd(&g_ssum[dst], efv);
    }
    efv = __shfl_sync(0xffffffffu, efv, 0);
    wr  = __shfl_sync(0xffffffffu, wr, 0);

    if (lane < 24) {
        float4 xs = ((const float4*)x)[(long)src * 24 + lane];
        red4(&g_fwdnum[(long)dst * 96 + lane * 4], xs.x * efv, xs.y * efv, xs.z * efv, xs.w * efv);
        float4 xd = ((const float4*)x)[(long)dst * 24 + lane];
        red4(&g_revagg[(long)src * 96 + lane * 4], xd.x * wr, xd.y * wr, xd.z * wr, xd.w * wr);
    }
}

__global__ void fwdw_kernel(const int* __restrict__ ei, float* __restrict__ out)
{
    long e = (long)blockIdx.x * blockDim.x + threadIdx.x;
    if (e >= N_EDGES) return;
    int dst = ei[N_EDGES + e];
    out[OFF_FW + e] = g_expf[e] / (g_ssum[dst] + 1e-9f);
}

__global__ void build_gatein(const float* __restrict__ x)
{
    long idx = (long)blockIdx.x * blockDim.x + threadIdx.x;
    long total = (long)N_NODES * 288;
    for (; idx < total; idx += (long)gridDim.x * blockDim.x) {
        int n = (int)(idx / 288), c = (int)(idx % 288);
        float v;
        if (c < 96)       v = x[(long)n * 96 + c];
        else if (c < 192) v = g_fwdnum[(long)n * 96 + (c - 96)] / (g_ssum[n] + 1e-9f);
        else              v = g_revagg[(long)n * 96 + (c - 192)];
        g_gatein[idx] = v;
    }
}

__global__ void build_candin(const float* __restrict__ x, const float* __restrict__ out)
{
    long idx = (long)blockIdx.x * blockDim.x + threadIdx.x;
    long total = (long)N_NODES * 288;
    for (; idx < total; idx += (long)gridDim.x * blockDim.x) {
        int n = (int)(idx / 288), c = (int)(idx % 288);
        float v;
        if (c < 96) v = out[OFF_R + (long)n * 96 + c] * x[(long)n * 96 + c];
        else        v = g_gatein[idx];
        g_candin[idx] = v;
    }
}

__global__ void update_kernel(const float* __restrict__ x, float* __restrict__ out)
{
    long idx = (long)blockIdx.x * blockDim.x + threadIdx.x;
    long total = (long)N_NODES * 96;
    if (idx >= total) return;
    float z = out[OFF_Z + idx];
    out[idx] = (1.0f - z) * x[idx] + z * g_cand[idx];
}

// ---------------- launcher ----------------
extern "C" void kernel_launch(void* const* d_in, const int* in_sizes, int n_in,
                              void* d_out, int out_size)
{
    const float* x     = (const float*)d_in[0];
    const float* x_s   = (const float*)d_in[1];
    const float* efeat = (const float*)d_in[2];
    const int*   ei    = (const int*)d_in[3];
    const float* fwdW1 = (const float*)d_in[4];
    const float* fwdb1 = (const float*)d_in[5];
    const float* fwdW2 = (const float*)d_in[6];
    const float* fwdb2 = (const float*)d_in[7];
    const float* revW1 = (const float*)d_in[8];
    const float* revb1 = (const float*)d_in[9];
    const float* revW2 = (const float*)d_in[10];
    const float* revb2 = (const float*)d_in[11];
    const float* rstW1 = (const float*)d_in[12];
    const float* rstb1 = (const float*)d_in[13];
    const float* rstW2 = (const float*)d_in[14];
    const float* rstb2 = (const float*)d_in[15];
    const float* updW1 = (const float*)d_in[16];
    const float* updb1 = (const float*)d_in[17];
    const float* updW2 = (const float*)d_in[18];
    const float* updb2 = (const float*)d_in[19];
    const float* cndW1 = (const float*)d_in[20];
    const float* cndb1 = (const float*)d_in[21];
    const float* cndW2 = (const float*)d_in[22];
    const float* cndb2 = (const float*)d_in[23];
    float* out = (float*)d_out;

    float *p_u, *p_Wpack, *p_bpack, *p_W1e, *p_table, *p_pe, *p_gatein, *p_candin, *p_h, *p_cand;
    cudaGetSymbolAddress((void**)&p_u, g_u);
    cudaGetSymbolAddress((void**)&p_Wpack, g_Wpack);
    cudaGetSymbolAddress((void**)&p_bpack, g_bpack);
    cudaGetSymbolAddress((void**)&p_W1e, g_W1e);
    cudaGetSymbolAddress((void**)&p_table, g_table);
    cudaGetSymbolAddress((void**)&p_pe, g_pe);
    cudaGetSymbolAddress((void**)&p_gatein, g_gatein);
    cudaGetSymbolAddress((void**)&p_candin, g_candin);
    cudaGetSymbolAddress((void**)&p_h, g_h);
    cudaGetSymbolAddress((void**)&p_cand, g_cand);

    const int MB_N = (N_NODES + MT - 1) / MT;   // 782
    const int MB_E = (N_EDGES + MT - 1) / MT;   // 12500

    // 1. pack weights + inputs
    pack_node_weights<<<432, 256>>>(fwdW1, revW1, fwdb1, revb1);
    pack_edge_weights<<<36, 256>>>(fwdW1, revW1);
    build_u<<<7040, 256>>>(x, x_s);
    zero_accum<<<9432, 256>>>();

    // 2. node table: [50000,144] @ [768,144]^T -> [50000,768]
    mma_gemm<<<dim3(768 / NT, MB_N), 128>>>(p_u, p_Wpack, p_bpack, p_table,
                                            N_NODES, 144, 768, 0);
    // 3. edge-feature projection: [800000,24] @ [384,24]^T -> [800000,384]
    mma_gemm<<<dim3(384 / NT, MB_E), 128>>>(efeat, p_W1e, nullptr, p_pe,
                                            N_EDGES, 24, 384, 0);
    // 4. edge pass: attention scores + aggregations
    edge_kernel<<<N_EDGES / 8, 256>>>(ei, x, fwdW2, fwdb2, revW2, revb2, out);
    // 5. normalized fwd weights
    fwdw_kernel<<<(N_EDGES + 255) / 256, 256>>>(ei, out);
    // 6. GRU (tf32 mma GEMMs)
    build_gatein<<<14063, 256>>>(x);
    mma_gemm<<<dim3(5, MB_N), 128>>>(p_gatein, rstW1, rstb1, p_h, N_NODES, 288, 288, 1);
    mma_gemm<<<dim3(2, MB_N), 128>>>(p_h, rstW2, rstb2, out + OFF_R, N_NODES, 288, 96, 2);
    mma_gemm<<<dim3(5, MB_N), 128>>>(p_gatein, updW1, updb1, p_h, N_NODES, 288, 288, 1);
    mma_gemm<<<dim3(2, MB_N), 128>>>(p_h, updW2, updb2, out + OFF_Z, N_NODES, 288, 96, 2);
    build_candin<<<14063, 256>>>(x, out);
    mma_gemm<<<dim3(5, MB_N), 128>>>(p_candin, cndW1, cndb1, p_h, N_NODES, 288, 288, 1);
    mma_gemm<<<dim3(2, MB_N), 128>>>(p_h, cndW2, cndb2, p_cand, N_NODES, 288, 96, 3);
    update_kernel<<<(N_NODES * 96 + 255) / 256, 256>>>(x, out);
}

// round 15
// speedup vs baseline: 1.9085x; 1.4958x over previous
#include <cuda_runtime.h>
#include <cuda_fp16.h>
#include <math.h>

#define N_NODES 50000
#define N_EDGES 800000
#define HDIM 96
#define SDIM 48
#define FDIM 24

// output layout: update[N*96] | fwd_w[E] | rev_w[E] | z[N*96] | r[N*96]
#define OFF_FW 4800000L
#define OFF_RW 5600000L
#define OFF_Z  6400000L
#define OFF_R  11200000L

typedef unsigned int u32;
typedef unsigned long long u64;

// ---------------- scratch (__device__ globals; no allocation allowed) ----------------
__device__ float  g_u[N_NODES * 144];          // [x | x_s]
__device__ float  g_Wpack[768 * 144];          // node-projection weights [M=768, K=144]
__device__ float  g_bpack[768];                // b1f baked into Sf, b1r into Br
__device__ float  g_W1e[384 * 24];             // edge-feature projection weights
__device__ __half g_table[N_NODES * 768];      // per node: Sf(192)|Br(192)|Df(192)|Ar(192)
__device__ __half g_pe[N_EDGES * 384];         // per edge: pe_f(192)|pe_r(192)
__device__ float  g_expf[N_EDGES];             // exp(score_fwd)
__device__ float  g_ssum[N_NODES];             // softmax denominators
__device__ float  g_fwdnum[N_NODES * HDIM];    // softmax-weighted numerator
__device__ float  g_revagg[N_NODES * HDIM];    // sigmoid-weighted rev aggregation
__device__ __half g_gatein[N_NODES * 288];
__device__ __half g_candin[N_NODES * 288];
__device__ __half g_h[N_NODES * 288];
__device__ float  g_cand[N_NODES * HDIM];

// ---------------- small helpers ----------------
__device__ __forceinline__ void red4(float* p, float a, float b, float c, float d) {
    asm volatile("red.global.add.v4.f32 [%0], {%1,%2,%3,%4};"
                 :: "l"(p), "f"(a), "f"(b), "f"(c), "f"(d) : "memory");
}

__device__ __forceinline__ u32 f2tf(float f) {
    u32 r;
    asm("cvt.rna.tf32.f32 %0, %1;" : "=r"(r) : "f"(f));
    return r;
}

// vec4 loads as float4, generic over element type
__device__ __forceinline__ float4 ld4(const float* p) { return *(const float4*)p; }
__device__ __forceinline__ float4 ld4(const __half* p) {
    __half2 h0 = *(const __half2*)p;
    __half2 h1 = *(const __half2*)(p + 2);
    float2 a = __half22float2(h0), b = __half22float2(h1);
    return make_float4(a.x, a.y, b.x, b.y);
}

// ---------------- weight packing ----------------
__global__ void pack_node_weights(const float* __restrict__ fwdW1, const float* __restrict__ revW1,
                                  const float* __restrict__ fwdb1, const float* __restrict__ revb1)
{
    int idx = blockIdx.x * blockDim.x + threadIdx.x;
    int total = 768 * 144;
    for (; idx < total; idx += gridDim.x * blockDim.x) {
        int j = idx / 144;     // output unit (0..767)
        int k = idx % 144;     // node-feature index: 0..95 -> x, 96..143 -> x_s
        float v;
        if (j < 192) {                       // Sf: fwd, "s" side
            v = (k < 96) ? fwdW1[j * 312 + k] : fwdW1[j * 312 + 192 + (k - 96)];
        } else if (j < 384) {                // Br: rev, "d" side (applied at src)
            int j2 = j - 192;
            v = (k < 96) ? revW1[j2 * 312 + 96 + k] : revW1[j2 * 312 + 240 + (k - 96)];
        } else if (j < 576) {                // Df: fwd, "d" side
            int j3 = j - 384;
            v = (k < 96) ? fwdW1[j3 * 312 + 96 + k] : fwdW1[j3 * 312 + 240 + (k - 96)];
        } else {                             // Ar: rev, "s" side (applied at dest)
            int j4 = j - 576;
            v = (k < 96) ? revW1[j4 * 312 + k] : revW1[j4 * 312 + 192 + (k - 96)];
        }
        g_Wpack[j * 144 + k] = v;
        if (k == 0) {
            g_bpack[j] = (j < 192) ? fwdb1[j] : ((j < 384) ? revb1[j - 192] : 0.0f);
        }
    }
}

__global__ void pack_edge_weights(const float* __restrict__ fwdW1, const float* __restrict__ revW1)
{
    int idx = blockIdx.x * blockDim.x + threadIdx.x;
    if (idx >= 384 * 24) return;
    int j = idx / 24, k = idx % 24;
    g_W1e[idx] = (j < 192) ? fwdW1[j * 312 + 288 + k] : revW1[(j - 192) * 312 + 288 + k];
}

__global__ void build_u(const float* __restrict__ x, const float* __restrict__ x_s)
{
    long idx = (long)blockIdx.x * blockDim.x + threadIdx.x;
    long total = (long)N_NODES * 144;
    for (; idx < total; idx += (long)gridDim.x * blockDim.x) {
        int n = (int)(idx / 144), c = (int)(idx % 144);
        g_u[idx] = (c < 96) ? x[(long)n * 96 + c] : x_s[(long)n * 48 + (c - 96)];
    }
}

__global__ void zero_accum()
{
    long idx = (long)blockIdx.x * blockDim.x + threadIdx.x;
    long total = (long)N_NODES * (1 + 2 * HDIM);
    for (; idx < total; idx += (long)gridDim.x * blockDim.x) {
        if (idx < N_NODES) g_ssum[idx] = 0.0f;
        else if (idx < (long)N_NODES * (1 + HDIM)) g_fwdnum[idx - N_NODES] = 0.0f;
        else g_revagg[idx - (long)N_NODES * (1 + HDIM)] = 0.0f;
    }
}

// ============================================================================
// mma.sync tf32 GEMM:  C[r, 0..M) = act( A[r, 0..K) @ W[m, 0..K)^T + bias )
// CTA tile 64x64, 4 warps of 32x32 (2x4 m16n8k8 frags), K chunked by 32.
// KPAD=36 -> fragment smem reads are bank-conflict-free permutations.
// TA/TC in {float, __half}. K must be a multiple of 4.
// acts: 0=none 1=relu 2=sigmoid 3=tanh
// ============================================================================
#define MT 64
#define NT 64
#define KC 32
#define KPAD 36

template <typename TA, typename TC>
__global__ __launch_bounds__(128)
void mma_gemm(const TA* __restrict__ A, const float* __restrict__ W,
              const float* __restrict__ bias, TC* __restrict__ C,
              int Nrows, int K, int M, int act)
{
    __shared__ u32 sA[MT * KPAD];
    __shared__ u32 sW[NT * KPAD];
    int tid = threadIdx.x;
    int warp = tid >> 5, lane = tid & 31;
    int qr = lane >> 2, qc = lane & 3;
    int m_off = (warp & 1) << 5;
    int n_off = (warp >> 1) << 5;
    long row0 = (long)blockIdx.y * MT;
    int col0 = blockIdx.x * NT;

    float acc[2][4][4];
#pragma unroll
    for (int mf = 0; mf < 2; mf++)
#pragma unroll
        for (int nf = 0; nf < 4; nf++)
#pragma unroll
            for (int i = 0; i < 4; i++) acc[mf][nf][i] = 0.0f;

    for (int k0 = 0; k0 < K; k0 += KC) {
        // ---- A chunk: 64 rows x 32 cols ----
#pragma unroll
        for (int i = 0; i < 4; i++) {
            int s = tid + (i << 7);
            int r = s >> 3, q = (s & 7) << 2;
            long gr = row0 + r;
            int kk = k0 + q;
            float4 v = make_float4(0.f, 0.f, 0.f, 0.f);
            if (gr < Nrows && kk < K) v = ld4(A + gr * K + kk);
            *(uint4*)&sA[r * KPAD + q] = make_uint4(f2tf(v.x), f2tf(v.y), f2tf(v.z), f2tf(v.w));
        }
        // ---- W chunk: 64 out-channels x 32 cols ----
#pragma unroll
        for (int i = 0; i < 4; i++) {
            int s = tid + (i << 7);
            int r = s >> 3, q = (s & 7) << 2;
            int gc = col0 + r;
            int kk = k0 + q;
            float4 v = make_float4(0.f, 0.f, 0.f, 0.f);
            if (gc < M && kk < K) v = ld4(W + (long)gc * K + kk);
            *(uint4*)&sW[r * KPAD + q] = make_uint4(f2tf(v.x), f2tf(v.y), f2tf(v.z), f2tf(v.w));
        }
        __syncthreads();

#pragma unroll
        for (int ks = 0; ks < 4; ks++) {
            int kb = ks << 3;
            u32 a[2][4];
#pragma unroll
            for (int mf = 0; mf < 2; mf++) {
                int rb = (m_off + (mf << 4) + qr) * KPAD + kb + qc;
                a[mf][0] = sA[rb];
                a[mf][1] = sA[rb + 8 * KPAD];
                a[mf][2] = sA[rb + 4];
                a[mf][3] = sA[rb + 8 * KPAD + 4];
            }
#pragma unroll
            for (int nf = 0; nf < 4; nf++) {
                int rb = (n_off + (nf << 3) + qr) * KPAD + kb + qc;
                u32 b0 = sW[rb], b1 = sW[rb + 4];
#pragma unroll
                for (int mf = 0; mf < 2; mf++) {
                    asm("mma.sync.aligned.m16n8k8.row.col.f32.tf32.tf32.f32 "
                        "{%0,%1,%2,%3}, {%4,%5,%6,%7}, {%8,%9}, {%0,%1,%2,%3};"
                        : "+f"(acc[mf][nf][0]), "+f"(acc[mf][nf][1]),
                          "+f"(acc[mf][nf][2]), "+f"(acc[mf][nf][3])
                        : "r"(a[mf][0]), "r"(a[mf][1]), "r"(a[mf][2]), "r"(a[mf][3]),
                          "r"(b0), "r"(b1));
                }
            }
        }
        __syncthreads();
    }

    // ---- epilogue: bias + act, 2-wide stores ----
#pragma unroll
    for (int mf = 0; mf < 2; mf++) {
#pragma unroll
        for (int h = 0; h < 2; h++) {
            long gr = row0 + m_off + (mf << 4) + qr + h * 8;
            if (gr >= Nrows) continue;
#pragma unroll
            for (int nf = 0; nf < 4; nf++) {
                int gc = col0 + n_off + (nf << 3) + (qc << 1);
                if (gc >= M) continue;
                float v0 = acc[mf][nf][h * 2 + 0];
                float v1 = acc[mf][nf][h * 2 + 1];
                if (bias) { v0 += bias[gc]; v1 += bias[gc + 1]; }
                if (act == 1) { v0 = fmaxf(v0, 0.0f); v1 = fmaxf(v1, 0.0f); }
                else if (act == 2) {
                    v0 = 1.0f / (1.0f + expf(-v0));
                    v1 = 1.0f / (1.0f + expf(-v1));
                } else if (act == 3) { v0 = tanhf(v0); v1 = tanhf(v1); }
                TC* dst = C + gr * M + gc;
                if (sizeof(TC) == 4) {
                    *(float2*)dst = make_float2(v0, v1);
                } else {
                    *(__half2*)dst = __floats2half2_rn(v0, v1);
                }
            }
        }
    }
}

// ---------------- edge kernel: one warp per edge ----------------
__global__ __launch_bounds__(256)
void edge_kernel(const int* __restrict__ ei, const float* __restrict__ x,
                 const float* __restrict__ fwdW2, const float* __restrict__ fwdb2,
                 const float* __restrict__ revW2, const float* __restrict__ revb2,
                 float* __restrict__ out)
{
    __shared__ float sW2f[192], sW2r[192];
    int tid = threadIdx.x;
    if (tid < 192) { sW2f[tid] = fwdW2[tid]; sW2r[tid] = revW2[tid]; }
    __syncthreads();

    long e = (long)blockIdx.x * 8 + (tid >> 5);
    if (e >= N_EDGES) return;
    int lane = tid & 31;

    int src = ei[e];
    int dst = ei[N_EDGES + e];
    // layout (half2 units per node row of 384): Sf 0..96 | Br 96..192 | Df 192..288 | Ar 288..384
    const __half2* srow = (const __half2*)(g_table + (long)src * 768);
    const __half2* drow = (const __half2*)(g_table + (long)dst * 768);
    const __half2* pe2  = (const __half2*)(g_pe + e * 384); // fwd 0..96 | rev 96..192

    float dotf = 0.0f, dotr = 0.0f;
#pragma unroll
    for (int i = 0; i < 3; i++) {
        int j = lane + 32 * i;           // 0..95
        float2 sf = __half22float2(srow[j]);
        float2 df = __half22float2(drow[192 + j]);
        float2 pf = __half22float2(pe2[j]);
        dotf = fmaf(fmaxf(sf.x + df.x + pf.x, 0.0f), sW2f[2 * j], dotf);
        dotf = fmaf(fmaxf(sf.y + df.y + pf.y, 0.0f), sW2f[2 * j + 1], dotf);
        float2 sb = __half22float2(srow[96 + j]);
        float2 da = __half22float2(drow[288 + j]);
        float2 pr = __half22float2(pe2[96 + j]);
        dotr = fmaf(fmaxf(sb.x + da.x + pr.x, 0.0f), sW2r[2 * j], dotr);
        dotr = fmaf(fmaxf(sb.y + da.y + pr.y, 0.0f), sW2r[2 * j + 1], dotr);
    }
#pragma unroll
    for (int o = 16; o > 0; o >>= 1) {
        dotf += __shfl_down_sync(0xffffffffu, dotf, o);
        dotr += __shfl_down_sync(0xffffffffu, dotr, o);
    }

    float efv = 0.0f, wr = 0.0f;
    if (lane == 0) {
        float rawf = dotf + fwdb2[0];
        float score = (rawf >= 0.0f ? rawf : 0.01f * rawf) * (1.0f / sqrtf(96.0f));
        efv = expf(score);     // max-free softmax (scores are tiny; shift-invariant)
        float rawr = dotr + revb2[0];
        wr = 1.0f / (1.0f + expf(-rawr));
        g_expf[e] = efv;
        out[OFF_RW + e] = wr;
        atomicAdd(&g_ssum[dst], efv);
    }
    efv = __shfl_sync(0xffffffffu, efv, 0);
    wr  = __shfl_sync(0xffffffffu, wr, 0);

    if (lane < 24) {
        float4 xs = ((const float4*)x)[(long)src * 24 + lane];
        red4(&g_fwdnum[(long)dst * 96 + lane * 4], xs.x * efv, xs.y * efv, xs.z * efv, xs.w * efv);
        float4 xd = ((const float4*)x)[(long)dst * 24 + lane];
        red4(&g_revagg[(long)src * 96 + lane * 4], xd.x * wr, xd.y * wr, xd.z * wr, xd.w * wr);
    }
}

__global__ void fwdw_kernel(const int* __restrict__ ei, float* __restrict__ out)
{
    long e = (long)blockIdx.x * blockDim.x + threadIdx.x;
    if (e >= N_EDGES) return;
    int dst = ei[N_EDGES + e];
    out[OFF_FW + e] = g_expf[e] / (g_ssum[dst] + 1e-9f);
}

__global__ void build_gatein(const float* __restrict__ x)
{
    long idx = (long)blockIdx.x * blockDim.x + threadIdx.x;
    long total = (long)N_NODES * 288;
    for (; idx < total; idx += (long)gridDim.x * blockDim.x) {
        int n = (int)(idx / 288), c = (int)(idx % 288);
        float v;
        if (c < 96)       v = x[(long)n * 96 + c];
        else if (c < 192) v = g_fwdnum[(long)n * 96 + (c - 96)] / (g_ssum[n] + 1e-9f);
        else              v = g_revagg[(long)n * 96 + (c - 192)];
        g_gatein[idx] = __float2half(v);
    }
}

__global__ void build_candin(const float* __restrict__ x, const float* __restrict__ out)
{
    long idx = (long)blockIdx.x * blockDim.x + threadIdx.x;
    long total = (long)N_NODES * 288;
    for (; idx < total; idx += (long)gridDim.x * blockDim.x) {
        int n = (int)(idx / 288), c = (int)(idx % 288);
        if (c < 96) {
            float v = out[OFF_R + (long)n * 96 + c] * x[(long)n * 96 + c];
            g_candin[idx] = __float2half(v);
        } else {
            g_candin[idx] = g_gatein[idx];
        }
    }
}

__global__ void update_kernel(const float* __restrict__ x, float* __restrict__ out)
{
    long idx = (long)blockIdx.x * blockDim.x + threadIdx.x;
    long total = (long)N_NODES * 96;
    if (idx >= total) return;
    float z = out[OFF_Z + idx];
    out[idx] = (1.0f - z) * x[idx] + z * g_cand[idx];
}

// ---------------- launcher ----------------
extern "C" void kernel_launch(void* const* d_in, const int* in_sizes, int n_in,
                              void* d_out, int out_size)
{
    const float* x     = (const float*)d_in[0];
    const float* x_s   = (const float*)d_in[1];
    const float* efeat = (const float*)d_in[2];
    const int*   ei    = (const int*)d_in[3];
    const float* fwdW1 = (const float*)d_in[4];
    const float* fwdb1 = (const float*)d_in[5];
    const float* fwdW2 = (const float*)d_in[6];
    const float* fwdb2 = (const float*)d_in[7];
    const float* revW1 = (const float*)d_in[8];
    const float* revb1 = (const float*)d_in[9];
    const float* revW2 = (const float*)d_in[10];
    const float* revb2 = (const float*)d_in[11];
    const float* rstW1 = (const float*)d_in[12];
    const float* rstb1 = (const float*)d_in[13];
    const float* rstW2 = (const float*)d_in[14];
    const float* rstb2 = (const float*)d_in[15];
    const float* updW1 = (const float*)d_in[16];
    const float* updb1 = (const float*)d_in[17];
    const float* updW2 = (const float*)d_in[18];
    const float* updb2 = (const float*)d_in[19];
    const float* cndW1 = (const float*)d_in[20];
    const float* cndb1 = (const float*)d_in[21];
    const float* cndW2 = (const float*)d_in[22];
    const float* cndb2 = (const float*)d_in[23];
    float* out = (float*)d_out;

    float *p_u, *p_Wpack, *p_bpack, *p_W1e, *p_cand;
    __half *p_table, *p_pe, *p_gatein, *p_candin, *p_h;
    cudaGetSymbolAddress((void**)&p_u, g_u);
    cudaGetSymbolAddress((void**)&p_Wpack, g_Wpack);
    cudaGetSymbolAddress((void**)&p_bpack, g_bpack);
    cudaGetSymbolAddress((void**)&p_W1e, g_W1e);
    cudaGetSymbolAddress((void**)&p_table, g_table);
    cudaGetSymbolAddress((void**)&p_pe, g_pe);
    cudaGetSymbolAddress((void**)&p_gatein, g_gatein);
    cudaGetSymbolAddress((void**)&p_candin, g_candin);
    cudaGetSymbolAddress((void**)&p_h, g_h);
    cudaGetSymbolAddress((void**)&p_cand, g_cand);

    const int MB_N = (N_NODES + MT - 1) / MT;   // 782
    const int MB_E = (N_EDGES + MT - 1) / MT;   // 12500

    // 1. pack weights + inputs
    pack_node_weights<<<432, 256>>>(fwdW1, revW1, fwdb1, revb1);
    pack_edge_weights<<<36, 256>>>(fwdW1, revW1);
    build_u<<<7040, 256>>>(x, x_s);
    zero_accum<<<9432, 256>>>();

    // 2. node table: [50000,144] @ [768,144]^T -> [50000,768] fp16
    mma_gemm<float, __half><<<dim3(768 / NT, MB_N), 128>>>(p_u, p_Wpack, p_bpack, p_table,
                                                           N_NODES, 144, 768, 0);
    // 3. edge-feature projection: [800000,24] @ [384,24]^T -> [800000,384] fp16
    mma_gemm<float, __half><<<dim3(384 / NT, MB_E), 128>>>(efeat, p_W1e, nullptr, p_pe,
                                                           N_EDGES, 24, 384, 0);
    // 4. edge pass: attention scores + aggregations
    edge_kernel<<<N_EDGES / 8, 256>>>(ei, x, fwdW2, fwdb2, revW2, revb2, out);
    // 5. normalized fwd weights
    fwdw_kernel<<<(N_EDGES + 255) / 256, 256>>>(ei, out);
    // 6. GRU (tf32 mma GEMMs, fp16 intermediates)
    build_gatein<<<14063, 256>>>(x);
    mma_gemm<__half, __half><<<dim3(5, MB_N), 128>>>(p_gatein, rstW1, rstb1, p_h, N_NODES, 288, 288, 1);
    mma_gemm<__half, float ><<<dim3(2, MB_N), 128>>>(p_h, rstW2, rstb2, out + OFF_R, N_NODES, 288, 96, 2);
    mma_gemm<__half, __half><<<dim3(5, MB_N), 128>>>(p_gatein, updW1, updb1, p_h, N_NODES, 288, 288, 1);
    mma_gemm<__half, float ><<<dim3(2, MB_N), 128>>>(p_h, updW2, updb2, out + OFF_Z, N_NODES, 288, 96, 2);
    build_candin<<<14063, 256>>>(x, out);
    mma_gemm<__half, __half><<<dim3(5, MB_N), 128>>>(p_candin, cndW1, cndb1, p_h, N_NODES, 288, 288, 1);
    mma_gemm<__half, float ><<<dim3(2, MB_N), 128>>>(p_h, cndW2, cndb2, p_cand, N_NODES, 288, 96, 3);
    update_kernel<<<(N_NODES * 96 + 255) / 256, 256>>>(x, out);
}

// round 16
// speedup vs baseline: 2.7088x; 1.4194x over previous
#include <cuda_runtime.h>
#include <cuda_fp16.h>
#include <math.h>

#define N_NODES 50000
#define N_EDGES 800000
#define HDIM 96
#define SDIM 48
#define FDIM 24

// output layout: update[N*96] | fwd_w[E] | rev_w[E] | z[N*96] | r[N*96]
#define OFF_FW 4800000L
#define OFF_RW 5600000L
#define OFF_Z  6400000L
#define OFF_R  11200000L

typedef unsigned int u32;
typedef unsigned long long u64;

// ---------------- scratch (__device__ globals; no allocation allowed) ----------------
__device__ __align__(16) __half g_uh[N_NODES * 144];       // [x | x_s] fp16
__device__ __align__(16) __half g_efh[N_EDGES * 24];       // edge features fp16
__device__ __align__(16) __half g_Wpackh[768 * 144];       // node-projection weights fp16
__device__ float  g_bpack[768];                            // b1f baked into Sf, b1r into Br
__device__ __align__(16) __half g_W1eh[384 * 24];          // edge-feature projection weights
__device__ __align__(16) __half g_table[N_NODES * 768];    // per node: Sf|Br|Df|Ar (192 each)
__device__ __align__(16) __half g_pe[N_EDGES * 384];       // per edge: pe_f(192)|pe_r(192)
__device__ float  g_expf[N_EDGES];
__device__ float  g_ssum[N_NODES];
__device__ float  g_fwdnum[N_NODES * HDIM];
__device__ float  g_revagg[N_NODES * HDIM];
__device__ __align__(16) __half g_gatein[N_NODES * 288];
__device__ __align__(16) __half g_candin[N_NODES * 288];
__device__ __align__(16) __half g_h2[N_NODES * 576];       // fused reset|update hidden
__device__ __align__(16) __half g_h[N_NODES * 288];        // candidate hidden
__device__ float  g_cand[N_NODES * HDIM];
// fp16 GRU weights
__device__ __align__(16) __half g_Wg1[576 * 288];          // [rstW1; updW1]
__device__ float  g_bg1[576];                              // [rstb1; updb1]
__device__ __align__(16) __half g_Wc1[288 * 288];
__device__ __align__(16) __half g_W2r[96 * 288];
__device__ __align__(16) __half g_W2z[96 * 288];
__device__ __align__(16) __half g_W2c[96 * 288];

// ---------------- small helpers ----------------
__device__ __forceinline__ void red4(float* p, float a, float b, float c, float d) {
    asm volatile("red.global.add.v4.f32 [%0], {%1,%2,%3,%4};"
                 :: "l"(p), "f"(a), "f"(b), "f"(c), "f"(d) : "memory");
}

__device__ __forceinline__ void cpasync16(u32 dst, const void* src, int srcbytes) {
    asm volatile("cp.async.cg.shared.global [%0], [%1], 16, %2;"
                 :: "r"(dst), "l"(src), "r"(srcbytes));
}

// ---------------- weight packing ----------------
__global__ void pack_node_weights(const float* __restrict__ fwdW1, const float* __restrict__ revW1,
                                  const float* __restrict__ fwdb1, const float* __restrict__ revb1)
{
    int idx = blockIdx.x * blockDim.x + threadIdx.x;
    int total = 768 * 144;
    for (; idx < total; idx += gridDim.x * blockDim.x) {
        int j = idx / 144;     // output unit (0..767)
        int k = idx % 144;     // node-feature index: 0..95 -> x, 96..143 -> x_s
        float v;
        if (j < 192) {                       // Sf: fwd, "s" side
            v = (k < 96) ? fwdW1[j * 312 + k] : fwdW1[j * 312 + 192 + (k - 96)];
        } else if (j < 384) {                // Br: rev, "d" side (applied at src)
            int j2 = j - 192;
            v = (k < 96) ? revW1[j2 * 312 + 96 + k] : revW1[j2 * 312 + 240 + (k - 96)];
        } else if (j < 576) {                // Df: fwd, "d" side
            int j3 = j - 384;
            v = (k < 96) ? fwdW1[j3 * 312 + 96 + k] : fwdW1[j3 * 312 + 240 + (k - 96)];
        } else {                             // Ar: rev, "s" side (applied at dest)
            int j4 = j - 576;
            v = (k < 96) ? revW1[j4 * 312 + k] : revW1[j4 * 312 + 192 + (k - 96)];
        }
        g_Wpackh[j * 144 + k] = __float2half(v);
        if (k == 0) {
            g_bpack[j] = (j < 192) ? fwdb1[j] : ((j < 384) ? revb1[j - 192] : 0.0f);
        }
    }
}

__global__ void pack_edge_weights(const float* __restrict__ fwdW1, const float* __restrict__ revW1)
{
    int idx = blockIdx.x * blockDim.x + threadIdx.x;
    if (idx >= 384 * 24) return;
    int j = idx / 24, k = idx % 24;
    float v = (j < 192) ? fwdW1[j * 312 + 288 + k] : revW1[(j - 192) * 312 + 288 + k];
    g_W1eh[idx] = __float2half(v);
}

__global__ void pack_gru(const float* __restrict__ rstW1, const float* __restrict__ updW1,
                         const float* __restrict__ cndW1, const float* __restrict__ rstW2,
                         const float* __restrict__ updW2, const float* __restrict__ cndW2,
                         const float* __restrict__ rstb1, const float* __restrict__ updb1)
{
    const int S1 = 576 * 288, S2 = 288 * 288, S3 = 96 * 288;
    int total = S1 + S2 + 3 * S3 + 576;
    for (int idx = blockIdx.x * blockDim.x + threadIdx.x; idx < total;
         idx += gridDim.x * blockDim.x) {
        if (idx < S1) {
            int j = idx / 288, k = idx % 288;
            g_Wg1[idx] = __float2half(j < 288 ? rstW1[j * 288 + k] : updW1[(j - 288) * 288 + k]);
        } else if (idx < S1 + S2) {
            g_Wc1[idx - S1] = __float2half(cndW1[idx - S1]);
        } else if (idx < S1 + S2 + S3) {
            g_W2r[idx - S1 - S2] = __float2half(rstW2[idx - S1 - S2]);
        } else if (idx < S1 + S2 + 2 * S3) {
            g_W2z[idx - S1 - S2 - S3] = __float2half(updW2[idx - S1 - S2 - S3]);
        } else if (idx < S1 + S2 + 3 * S3) {
            g_W2c[idx - S1 - S2 - 2 * S3] = __float2half(cndW2[idx - S1 - S2 - 2 * S3]);
        } else {
            int j = idx - (S1 + S2 + 3 * S3);
            g_bg1[j] = (j < 288) ? rstb1[j] : updb1[j - 288];
        }
    }
}

__global__ void build_u(const float* __restrict__ x, const float* __restrict__ x_s)
{
    long idx = (long)blockIdx.x * blockDim.x + threadIdx.x;
    long total = (long)N_NODES * 144;
    for (; idx < total; idx += (long)gridDim.x * blockDim.x) {
        int n = (int)(idx / 144), c = (int)(idx % 144);
        float v = (c < 96) ? x[(long)n * 96 + c] : x_s[(long)n * 48 + (c - 96)];
        g_uh[idx] = __float2half(v);
    }
}

__global__ void conv_ef(const float* __restrict__ ef)
{
    long idx = (long)blockIdx.x * blockDim.x + threadIdx.x;
    long total = (long)N_EDGES * 24;
    for (; idx < total; idx += (long)gridDim.x * blockDim.x)
        g_efh[idx] = __float2half(ef[idx]);
}

__global__ void zero_accum()
{
    long idx = (long)blockIdx.x * blockDim.x + threadIdx.x;
    long total = (long)N_NODES * (1 + 2 * HDIM);
    for (; idx < total; idx += (long)gridDim.x * blockDim.x) {
        if (idx < N_NODES) g_ssum[idx] = 0.0f;
        else if (idx < (long)N_NODES * (1 + HDIM)) g_fwdnum[idx - N_NODES] = 0.0f;
        else g_revagg[idx - (long)N_NODES * (1 + HDIM)] = 0.0f;
    }
}

// ============================================================================
// fp16 mma GEMM (m16n8k16, fp32 accumulate), cp.async double-buffered.
// C[r, 0..M) = act( A[r, 0..K)@lda @ W[m, 0..K)^T + bias )
// CTA 64x64, 4 warps of 32x32 (2x4 frags). K chunked by 32 halves.
// PAD=20 u32/row -> conflict-free fragment reads.
// acts: 0=none 1=relu 2=sigmoid 3=tanh
// ============================================================================
#define MT 64
#define NT 64
#define KCH 32
#define PADU 20

template <typename TC>
__global__ __launch_bounds__(128)
void hgemm(const __half* __restrict__ A, int lda,
           const __half* __restrict__ W,
           const float* __restrict__ bias,
           TC* __restrict__ C, int ldc,
           int Nrows, int K, int M, int act)
{
    __shared__ u32 sA[2][MT * PADU];
    __shared__ u32 sW[2][NT * PADU];
    int tid = threadIdx.x;
    int warp = tid >> 5, lane = tid & 31;
    int qr = lane >> 2, qc = lane & 3;
    int m_off = (warp & 1) << 5;
    int n_off = (warp >> 1) << 5;
    long row0 = (long)blockIdx.y * MT;
    int col0 = blockIdx.x * NT;
    int nchunks = (K + KCH - 1) / KCH;

    u32 sA0 = (u32)__cvta_generic_to_shared(&sA[0][0]);
    u32 sW0 = (u32)__cvta_generic_to_shared(&sW[0][0]);

    float acc[2][4][4];
#pragma unroll
    for (int mf = 0; mf < 2; mf++)
#pragma unroll
        for (int nf = 0; nf < 4; nf++)
#pragma unroll
            for (int i = 0; i < 4; i++) acc[mf][nf][i] = 0.0f;

    // ---- async loader: chunk c into buffer buf ----
    auto loadbuf = [&](int c, int buf) {
        int k0 = c * KCH;
        u32 abase = sA0 + buf * (MT * PADU * 4);
        u32 wbase = sW0 + buf * (NT * PADU * 4);
#pragma unroll
        for (int i = 0; i < 2; i++) {
            int ch = tid + (i << 7);           // 0..255
            int r = ch >> 2, seg = ch & 3;
            int kk = k0 + seg * 8;
            long gr = row0 + r;
            int vb = 0;
            if (gr < Nrows && kk < K) vb = min(16, (K - kk) * 2);
            cpasync16(abase + (r * PADU + seg * 4) * 4, A + gr * lda + kk, vb);
        }
#pragma unroll
        for (int i = 0; i < 2; i++) {
            int ch = tid + (i << 7);
            int r = ch >> 2, seg = ch & 3;
            int kk = k0 + seg * 8;
            int gc = col0 + r;
            int vb = 0;
            if (gc < M && kk < K) vb = min(16, (K - kk) * 2);
            cpasync16(wbase + (r * PADU + seg * 4) * 4, W + (long)gc * K + kk, vb);
        }
        asm volatile("cp.async.commit_group;" ::: "memory");
    };

    loadbuf(0, 0);
    for (int c = 0; c < nchunks; c++) {
        int buf = c & 1;
        if (c + 1 < nchunks) {
            loadbuf(c + 1, buf ^ 1);
            asm volatile("cp.async.wait_group 1;" ::: "memory");
        } else {
            asm volatile("cp.async.wait_group 0;" ::: "memory");
        }
        __syncthreads();

        const u32* pA = &sA[buf][0];
        const u32* pW = &sW[buf][0];
#pragma unroll
        for (int ks = 0; ks < 2; ks++) {
            int kb = ks << 3;       // u32 offset of this k16 step
            u32 a[2][4];
#pragma unroll
            for (int mf = 0; mf < 2; mf++) {
                int rb = (m_off + (mf << 4) + qr) * PADU + kb + qc;
                a[mf][0] = pA[rb];
                a[mf][1] = pA[rb + 8 * PADU];
                a[mf][2] = pA[rb + 4];
                a[mf][3] = pA[rb + 8 * PADU + 4];
            }
#pragma unroll
            for (int nf = 0; nf < 4; nf++) {
                int rb = (n_off + (nf << 3) + qr) * PADU + kb + qc;
                u32 b0 = pW[rb], b1 = pW[rb + 4];
#pragma unroll
                for (int mf = 0; mf < 2; mf++) {
                    asm("mma.sync.aligned.m16n8k16.row.col.f32.f16.f16.f32 "
                        "{%0,%1,%2,%3}, {%4,%5,%6,%7}, {%8,%9}, {%0,%1,%2,%3};"
                        : "+f"(acc[mf][nf][0]), "+f"(acc[mf][nf][1]),
                          "+f"(acc[mf][nf][2]), "+f"(acc[mf][nf][3])
                        : "r"(a[mf][0]), "r"(a[mf][1]), "r"(a[mf][2]), "r"(a[mf][3]),
                          "r"(b0), "r"(b1));
                }
            }
        }
        __syncthreads();
    }

    // ---- epilogue: bias + act, 2-wide stores ----
#pragma unroll
    for (int mf = 0; mf < 2; mf++) {
#pragma unroll
        for (int h = 0; h < 2; h++) {
            long gr = row0 + m_off + (mf << 4) + qr + h * 8;
            if (gr >= Nrows) continue;
#pragma unroll
            for (int nf = 0; nf < 4; nf++) {
                int gc = col0 + n_off + (nf << 3) + (qc << 1);
                if (gc >= M) continue;
                float v0 = acc[mf][nf][h * 2 + 0];
                float v1 = acc[mf][nf][h * 2 + 1];
                if (bias) { v0 += bias[gc]; v1 += bias[gc + 1]; }
                if (act == 1) { v0 = fmaxf(v0, 0.0f); v1 = fmaxf(v1, 0.0f); }
                else if (act == 2) {
                    v0 = 1.0f / (1.0f + expf(-v0));
                    v1 = 1.0f / (1.0f + expf(-v1));
                } else if (act == 3) { v0 = tanhf(v0); v1 = tanhf(v1); }
                TC* dst = C + gr * ldc + gc;
                if (sizeof(TC) == 4) {
                    *(float2*)dst = make_float2(v0, v1);
                } else {
                    *(__half2*)dst = __floats2half2_rn(v0, v1);
                }
            }
        }
    }
}

// ---------------- edge kernel: one warp per edge ----------------
__global__ __launch_bounds__(256)
void edge_kernel(const int* __restrict__ ei, const float* __restrict__ x,
                 const float* __restrict__ fwdW2, const float* __restrict__ fwdb2,
                 const float* __restrict__ revW2, const float* __restrict__ revb2,
                 float* __restrict__ out)
{
    __shared__ float sW2f[192], sW2r[192];
    int tid = threadIdx.x;
    if (tid < 192) { sW2f[tid] = fwdW2[tid]; sW2r[tid] = revW2[tid]; }
    __syncthreads();

    long e = (long)blockIdx.x * 8 + (tid >> 5);
    if (e >= N_EDGES) return;
    int lane = tid & 31;

    int src = ei[e];
    int dst = ei[N_EDGES + e];
    const __half2* srow = (const __half2*)(g_table + (long)src * 768);
    const __half2* drow = (const __half2*)(g_table + (long)dst * 768);
    const __half2* pe2  = (const __half2*)(g_pe + e * 384);

    float dotf = 0.0f, dotr = 0.0f;
#pragma unroll
    for (int i = 0; i < 3; i++) {
        int j = lane + 32 * i;           // 0..95
        float2 sf = __half22float2(srow[j]);
        float2 df = __half22float2(drow[192 + j]);
        float2 pf = __half22float2(pe2[j]);
        dotf = fmaf(fmaxf(sf.x + df.x + pf.x, 0.0f), sW2f[2 * j], dotf);
        dotf = fmaf(fmaxf(sf.y + df.y + pf.y, 0.0f), sW2f[2 * j + 1], dotf);
        float2 sb = __half22float2(srow[96 + j]);
        float2 da = __half22float2(drow[288 + j]);
        float2 pr = __half22float2(pe2[96 + j]);
        dotr = fmaf(fmaxf(sb.x + da.x + pr.x, 0.0f), sW2r[2 * j], dotr);
        dotr = fmaf(fmaxf(sb.y + da.y + pr.y, 0.0f), sW2r[2 * j + 1], dotr);
    }
#pragma unroll
    for (int o = 16; o > 0; o >>= 1) {
        dotf += __shfl_down_sync(0xffffffffu, dotf, o);
        dotr += __shfl_down_sync(0xffffffffu, dotr, o);
    }

    float efv = 0.0f, wr = 0.0f;
    if (lane == 0) {
        float rawf = dotf + fwdb2[0];
        float score = (rawf >= 0.0f ? rawf : 0.01f * rawf) * (1.0f / sqrtf(96.0f));
        efv = expf(score);     // max-free softmax (scores are tiny; shift-invariant)
        float rawr = dotr + revb2[0];
        wr = 1.0f / (1.0f + expf(-rawr));
        g_expf[e] = efv;
        out[OFF_RW + e] = wr;
        atomicAdd(&g_ssum[dst], efv);
    }
    efv = __shfl_sync(0xffffffffu, efv, 0);
    wr  = __shfl_sync(0xffffffffu, wr, 0);

    if (lane < 24) {
        float4 xs = ((const float4*)x)[(long)src * 24 + lane];
        red4(&g_fwdnum[(long)dst * 96 + lane * 4], xs.x * efv, xs.y * efv, xs.z * efv, xs.w * efv);
        float4 xd = ((const float4*)x)[(long)dst * 24 + lane];
        red4(&g_revagg[(long)src * 96 + lane * 4], xd.x * wr, xd.y * wr, xd.z * wr, xd.w * wr);
    }
}

__global__ void fwdw_kernel(const int* __restrict__ ei, float* __restrict__ out)
{
    long e = (long)blockIdx.x * blockDim.x + threadIdx.x;
    if (e >= N_EDGES) return;
    int dst = ei[N_EDGES + e];
    out[OFF_FW + e] = g_expf[e] / (g_ssum[dst] + 1e-9f);
}

__global__ void build_gatein(const float* __restrict__ x)
{
    long idx = (long)blockIdx.x * blockDim.x + threadIdx.x;
    long total = (long)N_NODES * 288;
    for (; idx < total; idx += (long)gridDim.x * blockDim.x) {
        int n = (int)(idx / 288), c = (int)(idx % 288);
        float v;
        if (c < 96)       v = x[(long)n * 96 + c];
        else if (c < 192) v = g_fwdnum[(long)n * 96 + (c - 96)] / (g_ssum[n] + 1e-9f);
        else              v = g_revagg[(long)n * 96 + (c - 192)];
        g_gatein[idx] = __float2half(v);
    }
}

__global__ void build_candin(const float* __restrict__ x, const float* __restrict__ out)
{
    long idx = (long)blockIdx.x * blockDim.x + threadIdx.x;
    long total = (long)N_NODES * 288;
    for (; idx < total; idx += (long)gridDim.x * blockDim.x) {
        int n = (int)(idx / 288), c = (int)(idx % 288);
        if (c < 96) {
            float v = out[OFF_R + (long)n * 96 + c] * x[(long)n * 96 + c];
            g_candin[idx] = __float2half(v);
        } else {
            g_candin[idx] = g_gatein[idx];
        }
    }
}

__global__ void update_kernel(const float* __restrict__ x, float* __restrict__ out)
{
    long idx = (long)blockIdx.x * blockDim.x + threadIdx.x;
    long total = (long)N_NODES * 96;
    if (idx >= total) return;
    float z = out[OFF_Z + idx];
    out[idx] = (1.0f - z) * x[idx] + z * g_cand[idx];
}

// ---------------- launcher ----------------
extern "C" void kernel_launch(void* const* d_in, const int* in_sizes, int n_in,
                              void* d_out, int out_size)
{
    const float* x     = (const float*)d_in[0];
    const float* x_s   = (const float*)d_in[1];
    const float* efeat = (const float*)d_in[2];
    const int*   ei    = (const int*)d_in[3];
    const float* fwdW1 = (const float*)d_in[4];
    const float* fwdb1 = (const float*)d_in[5];
    const float* fwdW2 = (const float*)d_in[6];
    const float* fwdb2 = (const float*)d_in[7];
    const float* revW1 = (const float*)d_in[8];
    const float* revb1 = (const float*)d_in[9];
    const float* revW2 = (const float*)d_in[10];
    const float* revb2 = (const float*)d_in[11];
    const float* rstW1 = (const float*)d_in[12];
    const float* rstb1 = (const float*)d_in[13];
    const float* rstW2 = (const float*)d_in[14];
    const float* rstb2 = (const float*)d_in[15];
    const float* updW1 = (const float*)d_in[16];
    const float* updb1 = (const float*)d_in[17];
    const float* updW2 = (const float*)d_in[18];
    const float* updb2 = (const float*)d_in[19];
    const float* cndW1 = (const float*)d_in[20];
    const float* cndb1 = (const float*)d_in[21];
    const float* cndW2 = (const float*)d_in[22];
    const float* cndb2 = (const float*)d_in[23];
    float* out = (float*)d_out;

    float *p_bpack, *p_bg1, *p_cand;
    __half *p_uh, *p_efh, *p_Wpackh, *p_W1eh, *p_table, *p_pe;
    __half *p_gatein, *p_candin, *p_h2, *p_h, *p_Wg1, *p_Wc1, *p_W2r, *p_W2z, *p_W2c;
    cudaGetSymbolAddress((void**)&p_uh, g_uh);
    cudaGetSymbolAddress((void**)&p_efh, g_efh);
    cudaGetSymbolAddress((void**)&p_Wpackh, g_Wpackh);
    cudaGetSymbolAddress((void**)&p_bpack, g_bpack);
    cudaGetSymbolAddress((void**)&p_W1eh, g_W1eh);
    cudaGetSymbolAddress((void**)&p_table, g_table);
    cudaGetSymbolAddress((void**)&p_pe, g_pe);
    cudaGetSymbolAddress((void**)&p_gatein, g_gatein);
    cudaGetSymbolAddress((void**)&p_candin, g_candin);
    cudaGetSymbolAddress((void**)&p_h2, g_h2);
    cudaGetSymbolAddress((void**)&p_h, g_h);
    cudaGetSymbolAddress((void**)&p_cand, g_cand);
    cudaGetSymbolAddress((void**)&p_Wg1, g_Wg1);
    cudaGetSymbolAddress((void**)&p_bg1, g_bg1);
    cudaGetSymbolAddress((void**)&p_Wc1, g_Wc1);
    cudaGetSymbolAddress((void**)&p_W2r, g_W2r);
    cudaGetSymbolAddress((void**)&p_W2z, g_W2z);
    cudaGetSymbolAddress((void**)&p_W2c, g_W2c);

    const int MB_N = (N_NODES + MT - 1) / MT;   // 782
    const int MB_E = (N_EDGES + MT - 1) / MT;   // 12500

    // 1. pack weights + convert inputs
    pack_node_weights<<<432, 256>>>(fwdW1, revW1, fwdb1, revb1);
    pack_edge_weights<<<36, 256>>>(fwdW1, revW1);
    pack_gru<<<650, 256>>>(rstW1, updW1, cndW1, rstW2, updW2, cndW2, rstb1, updb1);
    build_u<<<7040, 256>>>(x, x_s);
    conv_ef<<<9375, 256>>>(efeat);
    zero_accum<<<9432, 256>>>();

    // 2. node table: [50000,144] @ [768,144]^T -> [50000,768] fp16
    hgemm<__half><<<dim3(768 / NT, MB_N), 128>>>(p_uh, 144, p_Wpackh, p_bpack,
                                                 p_table, 768, N_NODES, 144, 768, 0);
    // 3. edge-feature projection: [800000,24] @ [384,24]^T -> fp16
    hgemm<__half><<<dim3(384 / NT, MB_E), 128>>>(p_efh, 24, p_W1eh, nullptr,
                                                 p_pe, 384, N_EDGES, 24, 384, 0);
    // 4. edge pass
    edge_kernel<<<N_EDGES / 8, 256>>>(ei, x, fwdW2, fwdb2, revW2, revb2, out);
    // 5. normalized fwd weights
    fwdw_kernel<<<(N_EDGES + 255) / 256, 256>>>(ei, out);
    // 6. GRU
    build_gatein<<<14063, 256>>>(x);
    // fused reset+update layer 1: M=576
    hgemm<__half><<<dim3(576 / NT, MB_N), 128>>>(p_gatein, 288, p_Wg1, p_bg1,
                                                 p_h2, 576, N_NODES, 288, 576, 1);
    // layer 2 (reads h2 halves via lda=576)
    hgemm<float ><<<dim3(2, MB_N), 128>>>(p_h2, 576, p_W2r, rstb2,
                                          out + OFF_R, 96, N_NODES, 288, 96, 2);
    hgemm<float ><<<dim3(2, MB_N), 128>>>(p_h2 + 288, 576, p_W2z, updb2,
                                          out + OFF_Z, 96, N_NODES, 288, 96, 2);
    build_candin<<<14063, 256>>>(x, out);
    hgemm<__half><<<dim3(288 / NT + 1, MB_N), 128>>>(p_candin, 288, p_Wc1, cndb1,
                                                     p_h, 288, N_NODES, 288, 288, 1);
    hgemm<float ><<<dim3(2, MB_N), 128>>>(p_h, 288, p_W2c, cndb2,
                                          p_cand, 96, N_NODES, 288, 96, 3);
    update_kernel<<<(N_NODES * 96 + 255) / 256, 256>>>(x, out);
}